// round 5
// baseline (speedup 1.0000x reference)
#include <cuda_runtime.h>
#include <math.h>

#define BATCH   64
#define IN_F    512
#define OUT_F   512
#define BASIS   8
#define KB      9                  // 1 (silu/w slot) + BASIS
#define NSPLIT  19                 // split-K over i
#define CHUNK   27                 // 19*27 = 513 -> 1 zero-pad i-row
#define IPAD    (NSPLIT * CHUNK)   // 513
#define STAGE_I 9
#define NSTAGE  3                  // 27 / 9
#define OTILE   64
#define STAGE_KK (STAGE_I * KB)    // 81
#define SMSTRIDE 68                // padded smem row stride for basis transpose

// Scratch (__device__ globals; pad rows of g_A stay .bss-zero forever)
__device__ float g_A[IPAD * KB * BATCH];
__device__ float g_part[NSPLIT * BATCH * OUT_F];
__device__ unsigned g_ctr[OUT_F / OTILE];   // bss-zero; self-wrapping per call

__device__ __forceinline__ unsigned long long dupf(float v) {
    unsigned int b = __float_as_uint(v);
    return ((unsigned long long)b << 32) | (unsigned long long)b;
}
__device__ __forceinline__ void ffma2(unsigned long long& d,
                                      unsigned long long a,
                                      unsigned long long b) {
    asm("fma.rn.f32x2 %0, %1, %2, %0;" : "+l"(d) : "l"(a), "l"(b));
}
__device__ __forceinline__ float pick(unsigned long long u, int hi) {
    return __uint_as_float(hi ? (unsigned int)(u >> 32) : (unsigned int)u);
}

// ---------------------------------------------------------------------------
// Kernel 1: augmented basis  A[(i*9+k)][b]
//   k=0: silu(x);  k=1..8: T_k(clip(tanh x)) via Chebyshev recurrence.
//   Block = 4 i-columns x 64 batch. Coalesced loads; smem transpose;
//   fully coalesced float4 stores to g_A.
// ---------------------------------------------------------------------------
__global__ __launch_bounds__(256) void basis_kernel(const float* __restrict__ x) {
    __shared__ float sm[4 * KB * SMSTRIDE];   // row = di*9+k, 36 rows, stride 68
    const int i0 = blockIdx.x * 4;
    const int t  = threadIdx.x;
    const int di = t & 3;
    const int b  = t >> 2;

    float xv = x[b * IN_F + i0 + di];

    float sig = __fdividef(1.0f, 1.0f + __expf(-xv));
    // tanh(x) = 1 - 2/(1 + e^{2x}); finite at both extremes
    float tt = 1.0f - 2.0f * __fdividef(1.0f, 1.0f + __expf(2.0f * xv));
    tt = fminf(fmaxf(tt, -1.0f + 1e-6f), 1.0f - 1e-6f);

    float* s0 = sm + di * (KB * SMSTRIDE) + b;
    s0[0]        = xv * sig;   // silu slot (pairs with w)
    s0[SMSTRIDE] = tt;         // T_1
    float tkm2 = 1.0f, tkm1 = tt;
    #pragma unroll
    for (int k = 2; k <= BASIS; k++) {
        float tk = 2.0f * tt * tkm1 - tkm2;
        s0[k * SMSTRIDE] = tk;
        tkm2 = tkm1; tkm1 = tk;
    }
    __syncthreads();

    // 36 rows x 64 floats = 576 float4 coalesced stores
    for (int idx = t; idx < 4 * KB * 16; idx += 256) {
        int row = idx >> 4;         // 0..35  (= di*9 + k)
        int c4  = idx & 15;
        const float* sr = sm + row * SMSTRIDE + c4 * 4;
        float4 v = make_float4(sr[0], sr[1], sr[2], sr[3]);
        int di2 = row / KB, k2 = row % KB;
        ((float4*)(g_A + (i0 + di2) * (KB * BATCH) + k2 * BATCH))[c4] = v;
    }
}

// ---------------------------------------------------------------------------
// Kernel 2: split-K GEMM, f32x2-packed 4x4 micro-tiles, register-side dup,
//   with fused deterministic last-block reduction (no 3rd kernel).
//   grid (NSPLIT, 8) = 152 blocks (1 wave), 256 threads, 41.4 KB static smem.
// ---------------------------------------------------------------------------
__global__ __launch_bounds__(256) void gemm_kernel(const float* __restrict__ w,
                                                   const float* __restrict__ c,
                                                   float* __restrict__ out) {
    __shared__ float As[STAGE_KK * BATCH];   // [81][64] = 20736 B
    __shared__ float Cs[STAGE_KK * OTILE];   // [81][64] = 20736 B
    __shared__ unsigned isLast;

    const int s   = blockIdx.x;
    const int oy  = blockIdx.y;
    const int o0  = oy * OTILE;
    const int tid = threadIdx.x;
    const int bb4 = (tid & 15) * 4;
    const int oo4 = (tid >> 4) * 4;
    const int ibeg = s * CHUNK;

    float4 aReg[6];
    float  wReg[3];
    float4 cReg[3][2];

    unsigned long long acc[8];
    #pragma unroll
    for (int j = 0; j < 8; j++) acc[j] = 0ull;

    auto loadStage = [&](int istS) {
        const float4* srcA = (const float4*)(g_A + (size_t)istS * (KB * BATCH));
        #pragma unroll
        for (int j = 0; j < 6; j++) {
            int idx = tid + j * 256;
            aReg[j] = (idx < STAGE_KK * BATCH / 4) ? srcA[idx]
                                                   : make_float4(0.f, 0.f, 0.f, 0.f);
        }
        #pragma unroll
        for (int j = 0; j < 3; j++) {
            int p = tid + j * 256;
            if (p < STAGE_I * OTILE) {
                int ii = p >> 6, oc = p & 63;
                int i = istS + ii;
                int o = o0 + oc;
                if (i < IN_F) {
                    wReg[j] = w[i * OUT_F + o];
                    const float4* cp = (const float4*)(c + ((size_t)i * OUT_F + o) * BASIS);
                    cReg[j][0] = cp[0];
                    cReg[j][1] = cp[1];
                } else {
                    wReg[j] = 0.f;
                    cReg[j][0] = make_float4(0.f, 0.f, 0.f, 0.f);
                    cReg[j][1] = make_float4(0.f, 0.f, 0.f, 0.f);
                }
            }
        }
    };

    auto storeStage = [&]() {
        #pragma unroll
        for (int j = 0; j < 6; j++) {
            int idx = tid + j * 256;
            if (idx < STAGE_KK * BATCH / 4) ((float4*)As)[idx] = aReg[j];
        }
        #pragma unroll
        for (int j = 0; j < 3; j++) {
            int p = tid + j * 256;
            if (p < STAGE_I * OTILE) {
                int ii = p >> 6, oc = p & 63;
                float* cs = Cs + ii * (KB * OTILE) + oc;
                float wv = wReg[j];
                cs[0 * OTILE] = wv;
                cs[1 * OTILE] = cReg[j][0].x * wv;
                cs[2 * OTILE] = cReg[j][0].y * wv;
                cs[3 * OTILE] = cReg[j][0].z * wv;
                cs[4 * OTILE] = cReg[j][0].w * wv;
                cs[5 * OTILE] = cReg[j][1].x * wv;
                cs[6 * OTILE] = cReg[j][1].y * wv;
                cs[7 * OTILE] = cReg[j][1].z * wv;
                cs[8 * OTILE] = cReg[j][1].w * wv;
            }
        }
    };

    auto compute = [&]() {
        #pragma unroll
        for (int kk = 0; kk < STAGE_KK; kk++) {
            ulonglong2 a = *(const ulonglong2*)&As[kk * BATCH + bb4];  // (b0,b1),(b2,b3)
            float4 cv    = *(const float4*)&Cs[kk * OTILE + oo4];      // 4 o-values
            unsigned long long c0 = dupf(cv.x), c1 = dupf(cv.y);
            unsigned long long c2 = dupf(cv.z), c3 = dupf(cv.w);
            ffma2(acc[0], a.x, c0); ffma2(acc[1], a.x, c1);
            ffma2(acc[2], a.x, c2); ffma2(acc[3], a.x, c3);
            ffma2(acc[4], a.y, c0); ffma2(acc[5], a.y, c1);
            ffma2(acc[6], a.y, c2); ffma2(acc[7], a.y, c3);
        }
    };

    // Software pipeline: STS current, sync, prefetch next G->R, compute, sync.
    loadStage(ibeg);
    #pragma unroll
    for (int st = 0; st < NSTAGE; st++) {
        storeStage();
        __syncthreads();
        if (st < NSTAGE - 1) loadStage(ibeg + (st + 1) * STAGE_I);
        compute();
        __syncthreads();
    }

    // Write split-K partial (float4 rows)
    float* pout = g_part + (size_t)s * (BATCH * OUT_F);
    #pragma unroll
    for (int r = 0; r < 4; r++) {
        const int b = bb4 + r;
        const int p = r >> 1;
        const int hi = r & 1;
        float4 v;
        v.x = pick(acc[p * 4 + 0], hi);
        v.y = pick(acc[p * 4 + 1], hi);
        v.z = pick(acc[p * 4 + 2], hi);
        v.w = pick(acc[p * 4 + 3], hi);
        *(float4*)&pout[b * OUT_F + o0 + oo4] = v;
    }

    // ---- deterministic last-block reduction for this o-column ----
    __syncthreads();
    if (tid == 0) {
        __threadfence();                                   // publish partial
        unsigned r = atomicInc(&g_ctr[oy], NSPLIT - 1);    // wraps to 0 -> replay-safe
        isLast = (r == NSPLIT - 1) ? 1u : 0u;
    }
    __syncthreads();
    if (isLast) {
        __threadfence();   // order reduction loads after counter observation
        // thread t sums o-float4 (tid&15) for 4 batches (tid>>4)*4 + r
        const int o4 = oy * (OTILE / 4) + (tid & 15);      // float4 index in [0,128)
        const float4* gp = (const float4*)g_part;
        #pragma unroll
        for (int r = 0; r < 4; r++) {
            const int b = (tid >> 4) * 4 + r;
            float4 sum = make_float4(0.f, 0.f, 0.f, 0.f);
            #pragma unroll
            for (int s2 = 0; s2 < NSPLIT; s2++) {
                float4 v = __ldcg(&gp[(size_t)s2 * (BATCH * OUT_F / 4) + b * (OUT_F / 4) + o4]);
                sum.x += v.x; sum.y += v.y; sum.z += v.z; sum.w += v.w;
            }
            ((float4*)out)[b * (OUT_F / 4) + o4] = sum;
        }
    }
}

// ---------------------------------------------------------------------------
extern "C" void kernel_launch(void* const* d_in, const int* in_sizes, int n_in,
                              void* d_out, int out_size) {
    const float* x = (const float*)d_in[0];   // (64, 512)
    const float* w = (const float*)d_in[1];   // (512, 512)
    const float* c = (const float*)d_in[2];   // (512, 512, 8)
    float* out = (float*)d_out;               // (64, 512)

    basis_kernel<<<IN_F / 4, 256>>>(x);
    gemm_kernel<<<dim3(NSPLIT, OUT_F / OTILE), 256>>>(w, c, out);
}

// round 6
// speedup vs baseline: 1.1564x; 1.1564x over previous
#include <cuda_runtime.h>
#include <math.h>

#define BATCH    64
#define IN_F     512
#define OUT_F    512
#define BASIS    8
#define KB       9                   // 1 (silu/w slot) + BASIS
#define NSPLIT   38                  // split-K over i
#define CHUNK    14                  // 38*14 = 532 -> 20 zero-pad i-rows
#define IPAD     (NSPLIT * CHUNK)    // 532
#define STAGE_I  7
#define NSTAGE   2                   // 14 / 7
#define OTILE    128
#define STAGE_KK (STAGE_I * KB)      // 63
#define NOTILE   (OUT_F / OTILE)     // 4
#define TOTBLK   (NSPLIT * NOTILE)   // 152
#define SMSTRIDE 68                  // padded row stride for basis transpose
#define RED_CHUNK 54                 // 54*152 >= 8192 output float4 slots

// Scratch (__device__ globals; pad rows of g_A stay .bss-zero forever)
__device__ float g_A[IPAD * KB * BATCH];              // 1.17 MB
__device__ float g_part[NSPLIT * BATCH * OUT_F];      // 5 MB
__device__ unsigned g_b0;    // basis-done arrivals   (reset each call)
__device__ unsigned g_arr;   // partial-done arrivals (reset each call)
__device__ unsigned g_done;  // self-wrapping exit counter

__device__ __forceinline__ unsigned long long dupf(float v) {
    unsigned int b = __float_as_uint(v);
    return ((unsigned long long)b << 32) | (unsigned long long)b;
}
__device__ __forceinline__ void ffma2(unsigned long long& d,
                                      unsigned long long a,
                                      unsigned long long b) {
    asm("fma.rn.f32x2 %0, %1, %2, %0;" : "+l"(d) : "l"(a), "l"(b));
}
__device__ __forceinline__ float pick(unsigned long long u, int hi) {
    return __uint_as_float(hi ? (unsigned int)(u >> 32) : (unsigned int)u);
}

// ---------------------------------------------------------------------------
// One persistent kernel: basis -> barrier -> split-K GEMM -> barrier ->
// distributed reduce.  grid (38, 4) = 152 blocks, 256 threads.
// ---------------------------------------------------------------------------
__global__ __launch_bounds__(256, 2)
void kan_kernel(const float* __restrict__ x,
                const float* __restrict__ w,
                const float* __restrict__ c,
                float* __restrict__ out) {
    __shared__ float As[STAGE_KK * BATCH];    // [63][64]  = 16128 B
    __shared__ float Cs[STAGE_KK * OTILE];    // [63][128] = 32256 B

    const int s   = blockIdx.x;
    const int oy  = blockIdx.y;
    const int o0  = oy * OTILE;
    const int tid = threadIdx.x;
    const int blkLinear = oy * NSPLIT + s;    // 0..151

    // ===== Phase 0: basis (blocks 0..127; 4 i-columns each) =====
    if (blkLinear < IN_F / 4) {
        const int i0 = blkLinear * 4;
        const int di = tid & 3;
        const int b  = tid >> 2;
        float xv = x[b * IN_F + i0 + di];

        float sig = __fdividef(1.0f, 1.0f + __expf(-xv));
        float tt  = 1.0f - 2.0f * __fdividef(1.0f, 1.0f + __expf(2.0f * xv));
        tt = fminf(fmaxf(tt, -1.0f + 1e-6f), 1.0f - 1e-6f);

        float* s0 = As + di * (KB * SMSTRIDE) + b;   // alias As as transpose buf
        s0[0]        = xv * sig;   // silu slot
        s0[SMSTRIDE] = tt;         // T_1
        float tkm2 = 1.0f, tkm1 = tt;
        #pragma unroll
        for (int k = 2; k <= BASIS; k++) {
            float tk = 2.0f * tt * tkm1 - tkm2;
            s0[k * SMSTRIDE] = tk;
            tkm2 = tkm1; tkm1 = tk;
        }
        __syncthreads();

        // 36 rows x 16 float4 coalesced stores to g_A
        for (int idx = tid; idx < 4 * KB * 16; idx += 256) {
            int row = idx >> 4;
            int c4  = idx & 15;
            const float* sr = As + row * SMSTRIDE + c4 * 4;
            float4 v = make_float4(sr[0], sr[1], sr[2], sr[3]);
            int di2 = row / KB, k2 = row % KB;
            ((float4*)(g_A + (i0 + di2) * (KB * BATCH) + k2 * BATCH))[c4] = v;
        }
        __syncthreads();
        if (tid == 0) { __threadfence(); atomicAdd(&g_b0, 1u); }
    }
    // grid-wide wait: basis complete
    if (tid == 0) { while (*(volatile unsigned*)&g_b0 != (unsigned)(IN_F / 4)) {} }
    __syncthreads();

    // ===== Phase 1: split-K GEMM, 4b x 8o micro-tiles =====
    const int bb4 = (tid & 15) * 4;    // 16 b-groups x 4
    const int oo8 = (tid >> 4) * 8;    // 16 o-groups x 8
    const int ibeg = s * CHUNK;

    float4 aReg[4];
    float  wReg[4];
    float4 cReg[4][2];

    unsigned long long acc[16];
    #pragma unroll
    for (int j = 0; j < 16; j++) acc[j] = 0ull;

    auto loadStage = [&](int istS) {
        const float4* srcA = (const float4*)(g_A + (size_t)istS * (KB * BATCH));
        #pragma unroll
        for (int j = 0; j < 4; j++) {
            int idx = tid + j * 256;
            aReg[j] = (idx < STAGE_KK * BATCH / 4) ? srcA[idx]
                                                   : make_float4(0.f, 0.f, 0.f, 0.f);
        }
        #pragma unroll
        for (int j = 0; j < 4; j++) {
            int p = tid + j * 256;
            if (p < STAGE_I * OTILE) {
                int ii = p >> 7, oc = p & 127;
                int i = istS + ii;
                int o = o0 + oc;
                if (i < IN_F) {
                    wReg[j] = w[i * OUT_F + o];
                    const float4* cp = (const float4*)(c + ((size_t)i * OUT_F + o) * BASIS);
                    cReg[j][0] = cp[0];
                    cReg[j][1] = cp[1];
                } else {
                    wReg[j] = 0.f;
                    cReg[j][0] = make_float4(0.f, 0.f, 0.f, 0.f);
                    cReg[j][1] = make_float4(0.f, 0.f, 0.f, 0.f);
                }
            }
        }
    };

    auto storeStage = [&]() {
        #pragma unroll
        for (int j = 0; j < 4; j++) {
            int idx = tid + j * 256;
            if (idx < STAGE_KK * BATCH / 4) ((float4*)As)[idx] = aReg[j];
        }
        #pragma unroll
        for (int j = 0; j < 4; j++) {
            int p = tid + j * 256;
            if (p < STAGE_I * OTILE) {
                int ii = p >> 7, oc = p & 127;
                float* cs = Cs + ii * (KB * OTILE) + oc;
                float wv = wReg[j];
                cs[0 * OTILE] = wv;
                cs[1 * OTILE] = cReg[j][0].x * wv;
                cs[2 * OTILE] = cReg[j][0].y * wv;
                cs[3 * OTILE] = cReg[j][0].z * wv;
                cs[4 * OTILE] = cReg[j][0].w * wv;
                cs[5 * OTILE] = cReg[j][1].x * wv;
                cs[6 * OTILE] = cReg[j][1].y * wv;
                cs[7 * OTILE] = cReg[j][1].z * wv;
                cs[8 * OTILE] = cReg[j][1].w * wv;
            }
        }
    };

    auto compute = [&]() {
        #pragma unroll 9
        for (int kk = 0; kk < STAGE_KK; kk++) {
            float4 av      = *(const float4*)&As[kk * BATCH + bb4];        // 4 b
            ulonglong2 c01 = *(const ulonglong2*)&Cs[kk * OTILE + oo8];    // o-pairs 0,1
            ulonglong2 c23 = *(const ulonglong2*)&Cs[kk * OTILE + oo8 + 4];// o-pairs 2,3
            unsigned long long a0 = dupf(av.x), a1 = dupf(av.y);
            unsigned long long a2 = dupf(av.z), a3 = dupf(av.w);
            ffma2(acc[0],  a0, c01.x); ffma2(acc[1],  a0, c01.y);
            ffma2(acc[2],  a0, c23.x); ffma2(acc[3],  a0, c23.y);
            ffma2(acc[4],  a1, c01.x); ffma2(acc[5],  a1, c01.y);
            ffma2(acc[6],  a1, c23.x); ffma2(acc[7],  a1, c23.y);
            ffma2(acc[8],  a2, c01.x); ffma2(acc[9],  a2, c01.y);
            ffma2(acc[10], a2, c23.x); ffma2(acc[11], a2, c23.y);
            ffma2(acc[12], a3, c01.x); ffma2(acc[13], a3, c01.y);
            ffma2(acc[14], a3, c23.x); ffma2(acc[15], a3, c23.y);
        }
    };

    loadStage(ibeg);
    #pragma unroll
    for (int st = 0; st < NSTAGE; st++) {
        storeStage();
        __syncthreads();
        if (st < NSTAGE - 1) loadStage(ibeg + (st + 1) * STAGE_I);
        compute();
        __syncthreads();
    }

    // write split-K partial: 4 batches x 8 o per thread
    float* pout = g_part + (size_t)s * (BATCH * OUT_F);
    #pragma unroll
    for (int r = 0; r < 4; r++) {
        const int b = bb4 + r;
        float4 v0, v1;
        v0.x = pick(acc[r * 4 + 0], 0); v0.y = pick(acc[r * 4 + 0], 1);
        v0.z = pick(acc[r * 4 + 1], 0); v0.w = pick(acc[r * 4 + 1], 1);
        v1.x = pick(acc[r * 4 + 2], 0); v1.y = pick(acc[r * 4 + 2], 1);
        v1.z = pick(acc[r * 4 + 3], 0); v1.w = pick(acc[r * 4 + 3], 1);
        *(float4*)&pout[b * OUT_F + o0 + oo8]     = v0;
        *(float4*)&pout[b * OUT_F + o0 + oo8 + 4] = v1;
    }

    // ===== Phase 2: grid-wide barrier, then distributed reduce =====
    __syncthreads();
    if (tid == 0) {
        __threadfence();
        atomicAdd(&g_arr, 1u);
        while (*(volatile unsigned*)&g_arr != (unsigned)TOTBLK) {}
    }
    __syncthreads();

    {
        const int slot = blkLinear * RED_CHUNK + tid;   // output float4 index
        if (tid < RED_CHUNK && slot < BATCH * OUT_F / 4) {
            const float4* gp = (const float4*)g_part;
            float4 sum = make_float4(0.f, 0.f, 0.f, 0.f);
            #pragma unroll
            for (int s2 = 0; s2 < NSPLIT; s2++) {
                float4 v = __ldcg(&gp[(size_t)s2 * (BATCH * OUT_F / 4) + slot]);
                sum.x += v.x; sum.y += v.y; sum.z += v.z; sum.w += v.w;
            }
            ((float4*)out)[slot] = sum;
        }
    }

    // reset counters for replay determinism (last block out resets)
    __syncthreads();
    if (tid == 0) {
        unsigned r = atomicInc(&g_done, TOTBLK - 1);   // wraps to 0
        if (r == TOTBLK - 1) {
            atomicExch(&g_arr, 0u);
            atomicExch(&g_b0, 0u);
        }
    }
}

// ---------------------------------------------------------------------------
extern "C" void kernel_launch(void* const* d_in, const int* in_sizes, int n_in,
                              void* d_out, int out_size) {
    const float* x = (const float*)d_in[0];   // (64, 512)
    const float* w = (const float*)d_in[1];   // (512, 512)
    const float* c = (const float*)d_in[2];   // (512, 512, 8)
    float* out = (float*)d_out;               // (64, 512)

    kan_kernel<<<dim3(NSPLIT, NOTILE), 256>>>(x, w, c, out);
}